// round 4
// baseline (speedup 1.0000x reference)
#include <cuda_runtime.h>
#include <cstdint>

#define LD 132   // padded smem row stride (floats): conflict-free fragment LDS

// Scratch: device globals (allocation-free rule).
__device__ float g_x_ji[38400000];   // [E,128]
__device__ float g_x_kj[38400000];   // [E,128]
__device__ float g_agg [38400000];   // [E,128] segment-sum accumulator

__device__ __forceinline__ uint32_t f2t(float f) {
    uint32_t u;
    asm("cvt.rna.tf32.f32 %0, %1;" : "=r"(u) : "f"(f));
    return u;
}
__device__ __forceinline__ float silu_f(float x) {
    return x / (1.0f + __expf(-x));
}
__device__ __forceinline__ void mma8(float c[4], const uint32_t a[4],
                                     uint32_t b0, uint32_t b1) {
    asm volatile(
        "mma.sync.aligned.m16n8k8.row.col.f32.tf32.tf32.f32 "
        "{%0,%1,%2,%3}, {%4,%5,%6,%7}, {%8,%9}, {%0,%1,%2,%3};\n"
        : "+f"(c[0]), "+f"(c[1]), "+f"(c[2]), "+f"(c[3])
        : "r"(a[0]), "r"(a[1]), "r"(a[2]), "r"(a[3]), "r"(b0), "r"(b1));
}

// ---------------------------------------------------------------------------
// K1: per-edge preproc. g_x_ji = silu(x@W_ji^T+b_ji); g_x_kj = silu(x@W_kj^T+b_kj)*rbf_h
// Also zeroes g_agg rows. Tile 128 edges x 128 out, 8 warps (4m x 2n), warp 32x64.
// ---------------------------------------------------------------------------
__global__ void __launch_bounds__(256, 1)
k_edge(const float* __restrict__ x, const float* __restrict__ rbf,
       const float* __restrict__ W_rbf,
       const float* __restrict__ W_kj, const float* __restrict__ b_kj,
       const float* __restrict__ W_ji, const float* __restrict__ b_ji, int E)
{
    extern __shared__ char smraw[];
    uint32_t* xs    = (uint32_t*)smraw;         // [128][LD] tf32 x tile
    uint32_t* ws    = xs + 128 * LD;            // [128][LD] weights, [n][k]
    float*    rbfs  = (float*)(ws + 128 * LD);  // [128*6]
    float*    wrbfs = rbfs + 128 * 6;           // [128*6]
    float*    bjs   = wrbfs + 128 * 6;          // [128]
    float*    bks   = bjs + 128;                // [128]

    const int tid = threadIdx.x, lane = tid & 31, wrp = tid >> 5;
    const int gid = lane >> 2, qid = lane & 3;
    const int mb = (wrp & 3) * 32, nb = (wrp >> 2) * 64;
    const int e0 = blockIdx.x * 128;
    const int rows = min(128, E - e0);

    for (int r = wrp; r < 128; r += 8) {
        float4 v = make_float4(0.f, 0.f, 0.f, 0.f);
        if (r < rows) v = *(const float4*)(x + (size_t)(e0 + r) * 128 + lane * 4);
        *(uint4*)(xs + r * LD + lane * 4) =
            make_uint4(f2t(v.x), f2t(v.y), f2t(v.z), f2t(v.w));
    }
    for (int i = tid; i < 128 * 6; i += 256) {
        int r = i / 6;
        rbfs[i]  = (r < rows) ? rbf[(size_t)(e0 + r) * 6 + (i - r * 6)] : 0.f;
        wrbfs[i] = W_rbf[i];
    }
    if (tid < 128) { bjs[tid] = b_ji[tid]; bks[tid] = b_kj[tid]; }
    {   // zero this tile's agg rows
        float4 z = make_float4(0.f, 0.f, 0.f, 0.f);
        for (int i = tid; i < 128 * 32; i += 256) {
            int r = i >> 5;
            if (r < rows)
                *(float4*)(g_agg + (size_t)(e0 + r) * 128 + (i & 31) * 4) = z;
        }
    }

    float acc[2][8][4];
    for (int pass = 0; pass < 2; ++pass) {
        const float* W = pass ? W_kj : W_ji;
        __syncthreads();
        for (int i = tid; i < 128 * 32; i += 256) {
            int n = i >> 5, k4 = (i & 31) * 4;
            float4 v = *(const float4*)(W + (size_t)n * 128 + k4);
            *(uint4*)(ws + n * LD + k4) =
                make_uint4(f2t(v.x), f2t(v.y), f2t(v.z), f2t(v.w));
        }
        __syncthreads();

        #pragma unroll
        for (int mt = 0; mt < 2; ++mt)
            #pragma unroll
            for (int nt = 0; nt < 8; ++nt)
                #pragma unroll
                for (int q = 0; q < 4; ++q) acc[mt][nt][q] = 0.f;

        for (int ks = 0; ks < 16; ++ks) {
            const int kc = ks * 8 + qid;
            uint32_t a[2][4];
            #pragma unroll
            for (int mt = 0; mt < 2; ++mt) {
                int r0 = mb + mt * 16 + gid;
                a[mt][0] = xs[r0 * LD + kc];
                a[mt][1] = xs[(r0 + 8) * LD + kc];
                a[mt][2] = xs[r0 * LD + kc + 4];
                a[mt][3] = xs[(r0 + 8) * LD + kc + 4];
            }
            #pragma unroll
            for (int nt = 0; nt < 8; ++nt) {
                int n = nb + nt * 8 + gid;
                uint32_t b0 = ws[n * LD + kc], b1 = ws[n * LD + kc + 4];
                mma8(acc[0][nt], a[0], b0, b1);
                mma8(acc[1][nt], a[1], b0, b1);
            }
        }

        float* dst = pass ? g_x_kj : g_x_ji;
        const float* bias = pass ? bks : bjs;
        #pragma unroll
        for (int mt = 0; mt < 2; ++mt) {
            #pragma unroll
            for (int half = 0; half < 2; ++half) {
                int r = mb + mt * 16 + gid + half * 8;
                if (r >= rows) continue;
                #pragma unroll
                for (int nt = 0; nt < 8; ++nt) {
                    int c = nb + nt * 8 + qid * 2;
                    float v0 = silu_f(acc[mt][nt][half * 2 + 0] + bias[c]);
                    float v1 = silu_f(acc[mt][nt][half * 2 + 1] + bias[c + 1]);
                    if (pass) {
                        float h0 = 0.f, h1 = 0.f;
                        #pragma unroll
                        for (int q = 0; q < 6; ++q) {
                            float rv = rbfs[r * 6 + q];
                            h0 += rv * wrbfs[c * 6 + q];
                            h1 += rv * wrbfs[(c + 1) * 6 + q];
                        }
                        v0 *= h0; v1 *= h1;
                    }
                    *(float2*)(dst + (size_t)(e0 + r) * 128 + c) = make_float2(v0, v1);
                }
            }
        }
    }
}

// ---------------------------------------------------------------------------
// K2: bilinear + scatter. 256 triplets x 128 out per CTA, 8 warps (4m x 2n),
// warp 64x64. K = 8 (j) x 128, per-row sbf_b scale folded into a-frag load.
// Scatter via red.global.add.v4.f32 into g_agg.
// ---------------------------------------------------------------------------
__global__ void __launch_bounds__(256, 1)
k_bil(const float* __restrict__ sbf, const int* __restrict__ idx_kj,
      const int* __restrict__ idx_ji, const float* __restrict__ W_sbf,
      const float* __restrict__ W_bil, int T)
{
    extern __shared__ char smraw[];
    float*    xg  = (float*)smraw;              // [256][LD] gathered x_kj (also staging/C)
    uint32_t* bjm = (uint32_t*)(xg + 256 * LD); // [128][LD] W_bil[:,j,:] tf32, [n][k]
    float*    sbs = (float*)(bjm + 128 * LD);   // [256][8] sbf_b
    int*      ikj = (int*)(sbs + 256 * 8);      // [256]
    int*      iji = ikj + 256;                  // [256]
    float*    wsb = (float*)(iji + 256);        // [8*42]

    const int tid = threadIdx.x, lane = tid & 31, wrp = tid >> 5;
    const int gid = lane >> 2, qid = lane & 3;
    const int mb = (wrp & 3) * 64, nb = (wrp >> 2) * 64;
    const int t0 = blockIdx.x * 256;
    const int rows = min(256, T - t0);

    if (tid < 256) {
        ikj[tid] = (tid < rows) ? idx_kj[t0 + tid] : 0;
        iji[tid] = (tid < rows) ? idx_ji[t0 + tid] : 0;
    }
    for (int i = tid; i < 8 * 42; i += 256) wsb[i] = W_sbf[i];
    // stage sbf rows linearly into xg region
    for (int i = tid; i < 256 * 42; i += 256)
        xg[i] = (i < rows * 42) ? sbf[(size_t)t0 * 42 + i] : 0.f;
    __syncthreads();
    // sbf_b = sbf @ W_sbf^T
    for (int i = tid; i < 256 * 8; i += 256) {
        int r = i >> 3, j = i & 7;
        float s = 0.f;
        #pragma unroll
        for (int q = 0; q < 42; ++q) s += xg[r * 42 + q] * wsb[j * 42 + q];
        sbs[i] = (r < rows) ? s : 0.f;
    }
    __syncthreads();
    // gather x_kj rows (float, unscaled)
    for (int r = wrp; r < 256; r += 8) {
        float4 v = make_float4(0.f, 0.f, 0.f, 0.f);
        if (r < rows) v = *(const float4*)(g_x_kj + (size_t)ikj[r] * 128 + lane * 4);
        *(float4*)(xg + r * LD + lane * 4) = v;
    }

    float acc[4][8][4];
    #pragma unroll
    for (int mt = 0; mt < 4; ++mt)
        #pragma unroll
        for (int nt = 0; nt < 8; ++nt)
            #pragma unroll
            for (int q = 0; q < 4; ++q) acc[mt][nt][q] = 0.f;

    for (int j = 0; j < 8; ++j) {
        __syncthreads();   // prior-j mma reads of bjm done (also covers gather on j=0)
        for (int i = tid; i < 128 * 32; i += 256) {
            int n = i >> 5, k4 = (i & 31) * 4;
            float4 v = *(const float4*)(W_bil + ((size_t)n * 8 + j) * 128 + k4);
            *(uint4*)(bjm + n * LD + k4) =
                make_uint4(f2t(v.x), f2t(v.y), f2t(v.z), f2t(v.w));
        }
        __syncthreads();

        float sc0[4], sc1[4];
        #pragma unroll
        for (int mt = 0; mt < 4; ++mt) {
            int r0 = mb + mt * 16 + gid;
            sc0[mt] = sbs[r0 * 8 + j];
            sc1[mt] = sbs[(r0 + 8) * 8 + j];
        }
        for (int ks = 0; ks < 16; ++ks) {
            const int kc = ks * 8 + qid;
            uint32_t a[4][4];
            #pragma unroll
            for (int mt = 0; mt < 4; ++mt) {
                int r0 = mb + mt * 16 + gid;
                a[mt][0] = f2t(xg[r0 * LD + kc]           * sc0[mt]);
                a[mt][1] = f2t(xg[(r0 + 8) * LD + kc]     * sc1[mt]);
                a[mt][2] = f2t(xg[r0 * LD + kc + 4]       * sc0[mt]);
                a[mt][3] = f2t(xg[(r0 + 8) * LD + kc + 4] * sc1[mt]);
            }
            #pragma unroll
            for (int nt = 0; nt < 8; ++nt) {
                int n = nb + nt * 8 + gid;
                uint32_t b0 = bjm[n * LD + kc], b1 = bjm[n * LD + kc + 4];
                #pragma unroll
                for (int mt = 0; mt < 4; ++mt) mma8(acc[mt][nt], a[mt], b0, b1);
            }
        }
    }

    __syncthreads();
    // stage C back into xg, then coalesced vector scatter
    #pragma unroll
    for (int mt = 0; mt < 4; ++mt) {
        #pragma unroll
        for (int nt = 0; nt < 8; ++nt) {
            int r0 = mb + mt * 16 + gid;
            int c = nb + nt * 8 + qid * 2;
            *(float2*)(xg + r0 * LD + c)       = make_float2(acc[mt][nt][0], acc[mt][nt][1]);
            *(float2*)(xg + (r0 + 8) * LD + c) = make_float2(acc[mt][nt][2], acc[mt][nt][3]);
        }
    }
    __syncthreads();
    for (int r = wrp; r < rows; r += 8) {
        float4 v = *(const float4*)(xg + r * LD + lane * 4);
        float* p = g_agg + (size_t)iji[r] * 128 + lane * 4;
        asm volatile("red.global.add.v4.f32 [%0], {%1,%2,%3,%4};"
                     :: "l"(p), "f"(v.x), "f"(v.y), "f"(v.z), "f"(v.w) : "memory");
    }
}

// ---------------------------------------------------------------------------
// K3: h = silu((x_ji + agg) @ W_lin^T + b_lin). Same tiling as K1, single pass.
// ---------------------------------------------------------------------------
__global__ void __launch_bounds__(256, 1)
k_out(const float* __restrict__ W_lin, const float* __restrict__ b_lin,
      float* __restrict__ out, int E)
{
    extern __shared__ char smraw[];
    uint32_t* xs = (uint32_t*)smraw;       // [128][LD]
    uint32_t* ws = xs + 128 * LD;          // [128][LD]
    float*    bl = (float*)(ws + 128 * LD);

    const int tid = threadIdx.x, lane = tid & 31, wrp = tid >> 5;
    const int gid = lane >> 2, qid = lane & 3;
    const int mb = (wrp & 3) * 32, nb = (wrp >> 2) * 64;
    const int e0 = blockIdx.x * 128;
    const int rows = min(128, E - e0);

    for (int r = wrp; r < 128; r += 8) {
        float4 v = make_float4(0.f, 0.f, 0.f, 0.f);
        if (r < rows) {
            float4 a = *(const float4*)(g_x_ji + (size_t)(e0 + r) * 128 + lane * 4);
            float4 b = *(const float4*)(g_agg  + (size_t)(e0 + r) * 128 + lane * 4);
            v = make_float4(a.x + b.x, a.y + b.y, a.z + b.z, a.w + b.w);
        }
        *(uint4*)(xs + r * LD + lane * 4) =
            make_uint4(f2t(v.x), f2t(v.y), f2t(v.z), f2t(v.w));
    }
    for (int i = tid; i < 128 * 32; i += 256) {
        int n = i >> 5, k4 = (i & 31) * 4;
        float4 v = *(const float4*)(W_lin + (size_t)n * 128 + k4);
        *(uint4*)(ws + n * LD + k4) =
            make_uint4(f2t(v.x), f2t(v.y), f2t(v.z), f2t(v.w));
    }
    if (tid < 128) bl[tid] = b_lin[tid];
    __syncthreads();

    float acc[2][8][4];
    #pragma unroll
    for (int mt = 0; mt < 2; ++mt)
        #pragma unroll
        for (int nt = 0; nt < 8; ++nt)
            #pragma unroll
            for (int q = 0; q < 4; ++q) acc[mt][nt][q] = 0.f;

    for (int ks = 0; ks < 16; ++ks) {
        const int kc = ks * 8 + qid;
        uint32_t a[2][4];
        #pragma unroll
        for (int mt = 0; mt < 2; ++mt) {
            int r0 = mb + mt * 16 + gid;
            a[mt][0] = xs[r0 * LD + kc];
            a[mt][1] = xs[(r0 + 8) * LD + kc];
            a[mt][2] = xs[r0 * LD + kc + 4];
            a[mt][3] = xs[(r0 + 8) * LD + kc + 4];
        }
        #pragma unroll
        for (int nt = 0; nt < 8; ++nt) {
            int n = nb + nt * 8 + gid;
            uint32_t b0 = ws[n * LD + kc], b1 = ws[n * LD + kc + 4];
            mma8(acc[0][nt], a[0], b0, b1);
            mma8(acc[1][nt], a[1], b0, b1);
        }
    }

    #pragma unroll
    for (int mt = 0; mt < 2; ++mt) {
        #pragma unroll
        for (int half = 0; half < 2; ++half) {
            int r = mb + mt * 16 + gid + half * 8;
            if (r >= rows) continue;
            #pragma unroll
            for (int nt = 0; nt < 8; ++nt) {
                int c = nb + nt * 8 + qid * 2;
                float v0 = silu_f(acc[mt][nt][half * 2 + 0] + bl[c]);
                float v1 = silu_f(acc[mt][nt][half * 2 + 1] + bl[c + 1]);
                *(float2*)(out + (size_t)(e0 + r) * 128 + c) = make_float2(v0, v1);
            }
        }
    }
}

// ---------------------------------------------------------------------------
extern "C" void kernel_launch(void* const* d_in, const int* in_sizes, int n_in,
                              void* d_out, int out_size)
{
    const float* x     = (const float*)d_in[0];
    const float* rbf   = (const float*)d_in[1];
    const float* sbf   = (const float*)d_in[2];
    const int*   ikj   = (const int*)d_in[3];
    const int*   iji   = (const int*)d_in[4];
    const float* W_rbf = (const float*)d_in[5];
    const float* W_sbf = (const float*)d_in[6];
    const float* W_kj  = (const float*)d_in[7];
    const float* b_kj  = (const float*)d_in[8];
    const float* W_ji  = (const float*)d_in[9];
    const float* b_ji  = (const float*)d_in[10];
    const float* W_bil = (const float*)d_in[11];
    const float* W_lin = (const float*)d_in[12];
    const float* b_lin = (const float*)d_in[13];

    const int E = in_sizes[0] / 128;
    const int T = in_sizes[3];

    const int SM1 = 128 * LD * 4 * 2 + 128 * 6 * 4 * 2 + 256 * 4;           // 142336
    const int SM2 = 256 * LD * 4 + 128 * LD * 4 + 256 * 8 * 4 + 512 * 4 + 8 * 42 * 4; // 214336
    const int SM3 = 128 * LD * 4 * 2 + 128 * 4;                             // 135680

    cudaFuncSetAttribute(k_edge, cudaFuncAttributeMaxDynamicSharedMemorySize, SM1);
    cudaFuncSetAttribute(k_bil,  cudaFuncAttributeMaxDynamicSharedMemorySize, SM2);
    cudaFuncSetAttribute(k_out,  cudaFuncAttributeMaxDynamicSharedMemorySize, SM3);

    dim3 blk(256);
    k_edge<<<(E + 127) / 128, blk, SM1>>>(x, rbf, W_rbf, W_kj, b_kj, W_ji, b_ji, E);
    k_bil <<<(T + 255) / 256, blk, SM2>>>(sbf, ikj, iji, W_sbf, W_bil, T);
    k_out <<<(E + 127) / 128, blk, SM3>>>(W_lin, b_lin, (float*)d_out, E);
}

// round 5
// speedup vs baseline: 1.2264x; 1.2264x over previous
#include <cuda_runtime.h>
#include <cstdint>

#define LD 132   // padded smem row stride (floats): conflict-free fragment LDS

// Scratch: device globals (allocation-free rule).
__device__ float g_x_ji[38400000];   // [E,128]
__device__ float g_x_kj[38400000];   // [E,128]
__device__ float g_agg [38400000];   // [E,128] segment-sum accumulator

__device__ __forceinline__ uint32_t f2t(float f) {
    uint32_t u;
    asm("cvt.rna.tf32.f32 %0, %1;" : "=r"(u) : "f"(f));
    return u;
}
__device__ __forceinline__ float silu_f(float x) {
    return x / (1.0f + __expf(-x));
}
__device__ __forceinline__ void mma8(float c[4], const uint32_t a[4],
                                     uint32_t b0, uint32_t b1) {
    asm volatile(
        "mma.sync.aligned.m16n8k8.row.col.f32.tf32.tf32.f32 "
        "{%0,%1,%2,%3}, {%4,%5,%6,%7}, {%8,%9}, {%0,%1,%2,%3};\n"
        : "+f"(c[0]), "+f"(c[1]), "+f"(c[2]), "+f"(c[3])
        : "r"(a[0]), "r"(a[1]), "r"(a[2]), "r"(a[3]), "r"(b0), "r"(b1));
}

// ---------------------------------------------------------------------------
// K1: per-edge preproc. g_x_ji = silu(x@W_ji^T+b_ji); g_x_kj = silu(x@W_kj^T+b_kj)*rbf_h
// Also zeroes g_agg rows. Tile 128x128, 512 threads = 16 warps (4m x 4n),
// warp tile 32x32.
// ---------------------------------------------------------------------------
__global__ void __launch_bounds__(512, 1)
k_edge(const float* __restrict__ x, const float* __restrict__ rbf,
       const float* __restrict__ W_rbf,
       const float* __restrict__ W_kj, const float* __restrict__ b_kj,
       const float* __restrict__ W_ji, const float* __restrict__ b_ji, int E)
{
    extern __shared__ char smraw[];
    uint32_t* xs    = (uint32_t*)smraw;         // [128][LD] tf32 x tile
    uint32_t* ws    = xs + 128 * LD;            // [128][LD] weights, [n][k]
    float*    rbfs  = (float*)(ws + 128 * LD);  // [128*6]
    float*    wrbfs = rbfs + 128 * 6;           // [128*6]
    float*    bjs   = wrbfs + 128 * 6;          // [128]
    float*    bks   = bjs + 128;                // [128]

    const int tid = threadIdx.x, lane = tid & 31, wrp = tid >> 5;
    const int gid = lane >> 2, qid = lane & 3;
    const int mb = (wrp & 3) * 32, nb = (wrp >> 2) * 32;
    const int e0 = blockIdx.x * 128;
    const int rows = min(128, E - e0);

    for (int r = wrp; r < 128; r += 16) {
        float4 v = make_float4(0.f, 0.f, 0.f, 0.f);
        if (r < rows) v = *(const float4*)(x + (size_t)(e0 + r) * 128 + lane * 4);
        *(uint4*)(xs + r * LD + lane * 4) =
            make_uint4(f2t(v.x), f2t(v.y), f2t(v.z), f2t(v.w));
    }
    for (int i = tid; i < 128 * 6; i += 512) {
        int r = i / 6;
        rbfs[i]  = (r < rows) ? rbf[(size_t)(e0 + r) * 6 + (i - r * 6)] : 0.f;
        wrbfs[i] = W_rbf[i];
    }
    if (tid < 128) { bjs[tid] = b_ji[tid]; bks[tid] = b_kj[tid]; }
    {   // zero this tile's agg rows
        float4 z = make_float4(0.f, 0.f, 0.f, 0.f);
        for (int i = tid; i < 128 * 32; i += 512) {
            int r = i >> 5;
            if (r < rows)
                *(float4*)(g_agg + (size_t)(e0 + r) * 128 + (i & 31) * 4) = z;
        }
    }

    float acc[2][4][4];
    for (int pass = 0; pass < 2; ++pass) {
        const float* W = pass ? W_kj : W_ji;
        __syncthreads();
        for (int i = tid; i < 128 * 32; i += 512) {
            int n = i >> 5, k4 = (i & 31) * 4;
            float4 v = *(const float4*)(W + (size_t)n * 128 + k4);
            *(uint4*)(ws + n * LD + k4) =
                make_uint4(f2t(v.x), f2t(v.y), f2t(v.z), f2t(v.w));
        }
        __syncthreads();

        #pragma unroll
        for (int mt = 0; mt < 2; ++mt)
            #pragma unroll
            for (int nt = 0; nt < 4; ++nt)
                #pragma unroll
                for (int q = 0; q < 4; ++q) acc[mt][nt][q] = 0.f;

        for (int ks = 0; ks < 16; ++ks) {
            const int kc = ks * 8 + qid;
            uint32_t a[2][4];
            #pragma unroll
            for (int mt = 0; mt < 2; ++mt) {
                int r0 = mb + mt * 16 + gid;
                a[mt][0] = xs[r0 * LD + kc];
                a[mt][1] = xs[(r0 + 8) * LD + kc];
                a[mt][2] = xs[r0 * LD + kc + 4];
                a[mt][3] = xs[(r0 + 8) * LD + kc + 4];
            }
            #pragma unroll
            for (int nt = 0; nt < 4; ++nt) {
                int n = nb + nt * 8 + gid;
                uint32_t b0 = ws[n * LD + kc], b1 = ws[n * LD + kc + 4];
                mma8(acc[0][nt], a[0], b0, b1);
                mma8(acc[1][nt], a[1], b0, b1);
            }
        }

        float* dst = pass ? g_x_kj : g_x_ji;
        const float* bias = pass ? bks : bjs;
        #pragma unroll
        for (int mt = 0; mt < 2; ++mt) {
            #pragma unroll
            for (int half = 0; half < 2; ++half) {
                int r = mb + mt * 16 + gid + half * 8;
                if (r >= rows) continue;
                #pragma unroll
                for (int nt = 0; nt < 4; ++nt) {
                    int c = nb + nt * 8 + qid * 2;
                    float v0 = silu_f(acc[mt][nt][half * 2 + 0] + bias[c]);
                    float v1 = silu_f(acc[mt][nt][half * 2 + 1] + bias[c + 1]);
                    if (pass) {
                        float h0 = 0.f, h1 = 0.f;
                        #pragma unroll
                        for (int q = 0; q < 6; ++q) {
                            float rv = rbfs[r * 6 + q];
                            h0 += rv * wrbfs[c * 6 + q];
                            h1 += rv * wrbfs[(c + 1) * 6 + q];
                        }
                        v0 *= h0; v1 *= h1;
                    }
                    *(float2*)(dst + (size_t)(e0 + r) * 128 + c) = make_float2(v0, v1);
                }
            }
        }
    }
}

// ---------------------------------------------------------------------------
// K2: bilinear + scatter. 256 triplets x 128 out per CTA, 512 threads =
// 16 warps (8m x 2n), warp tile 32x64. K = 8 (j) x 128, per-row sbf_b scale
// folded into a-frag load. Scatter via red.global.add.v4.f32 into g_agg.
// ---------------------------------------------------------------------------
__global__ void __launch_bounds__(512, 1)
k_bil(const float* __restrict__ sbf, const int* __restrict__ idx_kj,
      const int* __restrict__ idx_ji, const float* __restrict__ W_sbf,
      const float* __restrict__ W_bil, int T)
{
    extern __shared__ char smraw[];
    float*    xg  = (float*)smraw;              // [256][LD] gathered x_kj (also staging/C)
    uint32_t* bjm = (uint32_t*)(xg + 256 * LD); // [128][LD] W_bil[:,j,:] tf32, [n][k]
    float*    sbs = (float*)(bjm + 128 * LD);   // [256][8] sbf_b
    int*      ikj = (int*)(sbs + 256 * 8);      // [256]
    int*      iji = ikj + 256;                  // [256]
    float*    wsb = (float*)(iji + 256);        // [8*42]

    const int tid = threadIdx.x, lane = tid & 31, wrp = tid >> 5;
    const int gid = lane >> 2, qid = lane & 3;
    const int mb = (wrp & 7) * 32, nb = (wrp >> 3) * 64;
    const int t0 = blockIdx.x * 256;
    const int rows = min(256, T - t0);

    if (tid < 256) {
        ikj[tid] = (tid < rows) ? idx_kj[t0 + tid] : 0;
        iji[tid] = (tid < rows) ? idx_ji[t0 + tid] : 0;
    }
    for (int i = tid; i < 8 * 42; i += 512) wsb[i] = W_sbf[i];
    // stage sbf rows linearly into xg region
    for (int i = tid; i < 256 * 42; i += 512)
        xg[i] = (i < rows * 42) ? sbf[(size_t)t0 * 42 + i] : 0.f;
    __syncthreads();
    // sbf_b = sbf @ W_sbf^T
    for (int i = tid; i < 256 * 8; i += 512) {
        int r = i >> 3, j = i & 7;
        float s = 0.f;
        #pragma unroll
        for (int q = 0; q < 42; ++q) s += xg[r * 42 + q] * wsb[j * 42 + q];
        sbs[i] = (r < rows) ? s : 0.f;
    }
    __syncthreads();
    // gather x_kj rows (float, unscaled)
    for (int r = wrp; r < 256; r += 16) {
        float4 v = make_float4(0.f, 0.f, 0.f, 0.f);
        if (r < rows) v = *(const float4*)(g_x_kj + (size_t)ikj[r] * 128 + lane * 4);
        *(float4*)(xg + r * LD + lane * 4) = v;
    }

    float acc[2][8][4];
    #pragma unroll
    for (int mt = 0; mt < 2; ++mt)
        #pragma unroll
        for (int nt = 0; nt < 8; ++nt)
            #pragma unroll
            for (int q = 0; q < 4; ++q) acc[mt][nt][q] = 0.f;

    for (int j = 0; j < 8; ++j) {
        __syncthreads();   // prior-j mma reads of bjm done (also covers gather on j=0)
        for (int i = tid; i < 128 * 32; i += 512) {
            int n = i >> 5, k4 = (i & 31) * 4;
            float4 v = *(const float4*)(W_bil + ((size_t)n * 8 + j) * 128 + k4);
            *(uint4*)(bjm + n * LD + k4) =
                make_uint4(f2t(v.x), f2t(v.y), f2t(v.z), f2t(v.w));
        }
        __syncthreads();

        float sc0, sc1;
        {
            int r0 = mb + gid;
            sc0 = sbs[r0 * 8 + j];
            sc1 = sbs[(r0 + 8) * 8 + j];
        }
        float sc2, sc3;
        {
            int r0 = mb + 16 + gid;
            sc2 = sbs[r0 * 8 + j];
            sc3 = sbs[(r0 + 8) * 8 + j];
        }
        for (int ks = 0; ks < 16; ++ks) {
            const int kc = ks * 8 + qid;
            uint32_t a[2][4];
            {
                int r0 = mb + gid;
                a[0][0] = f2t(xg[r0 * LD + kc]           * sc0);
                a[0][1] = f2t(xg[(r0 + 8) * LD + kc]     * sc1);
                a[0][2] = f2t(xg[r0 * LD + kc + 4]       * sc0);
                a[0][3] = f2t(xg[(r0 + 8) * LD + kc + 4] * sc1);
                int r1 = mb + 16 + gid;
                a[1][0] = f2t(xg[r1 * LD + kc]           * sc2);
                a[1][1] = f2t(xg[(r1 + 8) * LD + kc]     * sc3);
                a[1][2] = f2t(xg[r1 * LD + kc + 4]       * sc2);
                a[1][3] = f2t(xg[(r1 + 8) * LD + kc + 4] * sc3);
            }
            #pragma unroll
            for (int nt = 0; nt < 8; ++nt) {
                int n = nb + nt * 8 + gid;
                uint32_t b0 = bjm[n * LD + kc], b1 = bjm[n * LD + kc + 4];
                mma8(acc[0][nt], a[0], b0, b1);
                mma8(acc[1][nt], a[1], b0, b1);
            }
        }
    }

    __syncthreads();
    // stage C back into xg, then coalesced vector scatter
    #pragma unroll
    for (int mt = 0; mt < 2; ++mt) {
        #pragma unroll
        for (int nt = 0; nt < 8; ++nt) {
            int r0 = mb + mt * 16 + gid;
            int c = nb + nt * 8 + qid * 2;
            *(float2*)(xg + r0 * LD + c)       = make_float2(acc[mt][nt][0], acc[mt][nt][1]);
            *(float2*)(xg + (r0 + 8) * LD + c) = make_float2(acc[mt][nt][2], acc[mt][nt][3]);
        }
    }
    __syncthreads();
    for (int r = wrp; r < rows; r += 16) {
        float4 v = *(const float4*)(xg + r * LD + lane * 4);
        float* p = g_agg + (size_t)iji[r] * 128 + lane * 4;
        asm volatile("red.global.add.v4.f32 [%0], {%1,%2,%3,%4};"
                     :: "l"(p), "f"(v.x), "f"(v.y), "f"(v.z), "f"(v.w) : "memory");
    }
}

// ---------------------------------------------------------------------------
// K3: h = silu((x_ji + agg) @ W_lin^T + b_lin). 512 threads, 4m x 4n warps.
// ---------------------------------------------------------------------------
__global__ void __launch_bounds__(512, 1)
k_out(const float* __restrict__ W_lin, const float* __restrict__ b_lin,
      float* __restrict__ out, int E)
{
    extern __shared__ char smraw[];
    uint32_t* xs = (uint32_t*)smraw;       // [128][LD]
    uint32_t* ws = xs + 128 * LD;          // [128][LD]
    float*    bl = (float*)(ws + 128 * LD);

    const int tid = threadIdx.x, lane = tid & 31, wrp = tid >> 5;
    const int gid = lane >> 2, qid = lane & 3;
    const int mb = (wrp & 3) * 32, nb = (wrp >> 2) * 32;
    const int e0 = blockIdx.x * 128;
    const int rows = min(128, E - e0);

    for (int r = wrp; r < 128; r += 16) {
        float4 v = make_float4(0.f, 0.f, 0.f, 0.f);
        if (r < rows) {
            float4 a = *(const float4*)(g_x_ji + (size_t)(e0 + r) * 128 + lane * 4);
            float4 b = *(const float4*)(g_agg  + (size_t)(e0 + r) * 128 + lane * 4);
            v = make_float4(a.x + b.x, a.y + b.y, a.z + b.z, a.w + b.w);
        }
        *(uint4*)(xs + r * LD + lane * 4) =
            make_uint4(f2t(v.x), f2t(v.y), f2t(v.z), f2t(v.w));
    }
    for (int i = tid; i < 128 * 32; i += 512) {
        int n = i >> 5, k4 = (i & 31) * 4;
        float4 v = *(const float4*)(W_lin + (size_t)n * 128 + k4);
        *(uint4*)(ws + n * LD + k4) =
            make_uint4(f2t(v.x), f2t(v.y), f2t(v.z), f2t(v.w));
    }
    if (tid < 128) bl[tid] = b_lin[tid];
    __syncthreads();

    float acc[2][4][4];
    #pragma unroll
    for (int mt = 0; mt < 2; ++mt)
        #pragma unroll
        for (int nt = 0; nt < 4; ++nt)
            #pragma unroll
            for (int q = 0; q < 4; ++q) acc[mt][nt][q] = 0.f;

    for (int ks = 0; ks < 16; ++ks) {
        const int kc = ks * 8 + qid;
        uint32_t a[2][4];
        #pragma unroll
        for (int mt = 0; mt < 2; ++mt) {
            int r0 = mb + mt * 16 + gid;
            a[mt][0] = xs[r0 * LD + kc];
            a[mt][1] = xs[(r0 + 8) * LD + kc];
            a[mt][2] = xs[r0 * LD + kc + 4];
            a[mt][3] = xs[(r0 + 8) * LD + kc + 4];
        }
        #pragma unroll
        for (int nt = 0; nt < 4; ++nt) {
            int n = nb + nt * 8 + gid;
            uint32_t b0 = ws[n * LD + kc], b1 = ws[n * LD + kc + 4];
            mma8(acc[0][nt], a[0], b0, b1);
            mma8(acc[1][nt], a[1], b0, b1);
        }
    }

    #pragma unroll
    for (int mt = 0; mt < 2; ++mt) {
        #pragma unroll
        for (int half = 0; half < 2; ++half) {
            int r = mb + mt * 16 + gid + half * 8;
            if (r >= rows) continue;
            #pragma unroll
            for (int nt = 0; nt < 4; ++nt) {
                int c = nb + nt * 8 + qid * 2;
                float v0 = silu_f(acc[mt][nt][half * 2 + 0] + bl[c]);
                float v1 = silu_f(acc[mt][nt][half * 2 + 1] + bl[c + 1]);
                *(float2*)(out + (size_t)(e0 + r) * 128 + c) = make_float2(v0, v1);
            }
        }
    }
}

// ---------------------------------------------------------------------------
extern "C" void kernel_launch(void* const* d_in, const int* in_sizes, int n_in,
                              void* d_out, int out_size)
{
    const float* x     = (const float*)d_in[0];
    const float* rbf   = (const float*)d_in[1];
    const float* sbf   = (const float*)d_in[2];
    const int*   ikj   = (const int*)d_in[3];
    const int*   iji   = (const int*)d_in[4];
    const float* W_rbf = (const float*)d_in[5];
    const float* W_sbf = (const float*)d_in[6];
    const float* W_kj  = (const float*)d_in[7];
    const float* b_kj  = (const float*)d_in[8];
    const float* W_ji  = (const float*)d_in[9];
    const float* b_ji  = (const float*)d_in[10];
    const float* W_bil = (const float*)d_in[11];
    const float* W_lin = (const float*)d_in[12];
    const float* b_lin = (const float*)d_in[13];

    const int E = in_sizes[0] / 128;
    const int T = in_sizes[3];

    const int SM1 = 128 * LD * 4 * 2 + 128 * 6 * 4 * 2 + 256 * 4;                     // 142336
    const int SM2 = 256 * LD * 4 + 128 * LD * 4 + 256 * 8 * 4 + 512 * 4 + 8 * 42 * 4; // 214336
    const int SM3 = 128 * LD * 4 * 2 + 128 * 4;                                       // 135680

    cudaFuncSetAttribute(k_edge, cudaFuncAttributeMaxDynamicSharedMemorySize, SM1);
    cudaFuncSetAttribute(k_bil,  cudaFuncAttributeMaxDynamicSharedMemorySize, SM2);
    cudaFuncSetAttribute(k_out,  cudaFuncAttributeMaxDynamicSharedMemorySize, SM3);

    dim3 blk(512);
    k_edge<<<(E + 127) / 128, blk, SM1>>>(x, rbf, W_rbf, W_kj, b_kj, W_ji, b_ji, E);
    k_bil <<<(T + 255) / 256, blk, SM2>>>(sbf, ikj, iji, W_sbf, W_bil, T);
    k_out <<<(E + 127) / 128, blk, SM3>>>(W_lin, b_lin, (float*)d_out, E);
}

// round 6
// speedup vs baseline: 1.2960x; 1.0568x over previous
#include <cuda_runtime.h>
#include <cstdint>

#define LD 132   // padded smem row stride (floats): conflict-free fragment LDS

// Scratch: device globals (allocation-free rule).
__device__ float g_x_kj[38400000];   // [E,128]
__device__ float g_agg [38400000];   // [E,128] x_ji + segment_sum accumulator

__device__ __forceinline__ uint32_t f2t(float f) {
    uint32_t u;
    asm("cvt.rna.tf32.f32 %0, %1;" : "=r"(u) : "f"(f));
    return u;
}
__device__ __forceinline__ float silu_f(float x) {
    return x / (1.0f + __expf(-x));
}
__device__ __forceinline__ void mma8(float c[4], const uint32_t a[4],
                                     uint32_t b0, uint32_t b1) {
    asm volatile(
        "mma.sync.aligned.m16n8k8.row.col.f32.tf32.tf32.f32 "
        "{%0,%1,%2,%3}, {%4,%5,%6,%7}, {%8,%9}, {%0,%1,%2,%3};\n"
        : "+f"(c[0]), "+f"(c[1]), "+f"(c[2]), "+f"(c[3])
        : "r"(a[0]), "r"(a[1]), "r"(a[2]), "r"(a[3]), "r"(b0), "r"(b1));
}

// ---------------------------------------------------------------------------
// K1: per-edge preproc.
//   g_agg  = silu(x@W_ji^T+b_ji)          (pass 0 — doubles as agg init)
//   g_x_kj = silu(x@W_kj^T+b_kj)*rbf_h    (pass 1)
// Tile 128x128, 512 threads = 16 warps (4m x 4n), warp tile 32x32.
// ---------------------------------------------------------------------------
__global__ void __launch_bounds__(512, 1)
k_edge(const float* __restrict__ x, const float* __restrict__ rbf,
       const float* __restrict__ W_rbf,
       const float* __restrict__ W_kj, const float* __restrict__ b_kj,
       const float* __restrict__ W_ji, const float* __restrict__ b_ji, int E)
{
    extern __shared__ char smraw[];
    uint32_t* xs    = (uint32_t*)smraw;         // [128][LD] tf32 x tile
    uint32_t* ws    = xs + 128 * LD;            // [128][LD] weights, [n][k]
    float*    rbfs  = (float*)(ws + 128 * LD);  // [128*6]
    float*    wrbfs = rbfs + 128 * 6;           // [128*6]
    float*    bjs   = wrbfs + 128 * 6;          // [128]
    float*    bks   = bjs + 128;                // [128]

    const int tid = threadIdx.x, lane = tid & 31, wrp = tid >> 5;
    const int gid = lane >> 2, qid = lane & 3;
    const int mb = (wrp & 3) * 32, nb = (wrp >> 2) * 32;
    const int e0 = blockIdx.x * 128;
    const int rows = min(128, E - e0);

    for (int r = wrp; r < 128; r += 16) {
        float4 v = make_float4(0.f, 0.f, 0.f, 0.f);
        if (r < rows) v = *(const float4*)(x + (size_t)(e0 + r) * 128 + lane * 4);
        *(uint4*)(xs + r * LD + lane * 4) =
            make_uint4(f2t(v.x), f2t(v.y), f2t(v.z), f2t(v.w));
    }
    for (int i = tid; i < 128 * 6; i += 512) {
        int r = i / 6;
        rbfs[i]  = (r < rows) ? rbf[(size_t)(e0 + r) * 6 + (i - r * 6)] : 0.f;
        wrbfs[i] = W_rbf[i];
    }
    if (tid < 128) { bjs[tid] = b_ji[tid]; bks[tid] = b_kj[tid]; }

    float acc[2][4][4];
    for (int pass = 0; pass < 2; ++pass) {
        const float* W = pass ? W_kj : W_ji;
        __syncthreads();
        for (int i = tid; i < 128 * 32; i += 512) {
            int n = i >> 5, k4 = (i & 31) * 4;
            float4 v = *(const float4*)(W + (size_t)n * 128 + k4);
            *(uint4*)(ws + n * LD + k4) =
                make_uint4(f2t(v.x), f2t(v.y), f2t(v.z), f2t(v.w));
        }
        __syncthreads();

        #pragma unroll
        for (int mt = 0; mt < 2; ++mt)
            #pragma unroll
            for (int nt = 0; nt < 4; ++nt)
                #pragma unroll
                for (int q = 0; q < 4; ++q) acc[mt][nt][q] = 0.f;

        #pragma unroll 4
        for (int ks = 0; ks < 16; ++ks) {
            const int kc = ks * 8 + qid;
            uint32_t a[2][4];
            #pragma unroll
            for (int mt = 0; mt < 2; ++mt) {
                int r0 = mb + mt * 16 + gid;
                a[mt][0] = xs[r0 * LD + kc];
                a[mt][1] = xs[(r0 + 8) * LD + kc];
                a[mt][2] = xs[r0 * LD + kc + 4];
                a[mt][3] = xs[(r0 + 8) * LD + kc + 4];
            }
            #pragma unroll
            for (int nt = 0; nt < 4; ++nt) {
                int n = nb + nt * 8 + gid;
                uint32_t b0 = ws[n * LD + kc], b1 = ws[n * LD + kc + 4];
                mma8(acc[0][nt], a[0], b0, b1);
                mma8(acc[1][nt], a[1], b0, b1);
            }
        }

        float* dst = pass ? g_x_kj : g_agg;
        const float* bias = pass ? bks : bjs;
        #pragma unroll
        for (int mt = 0; mt < 2; ++mt) {
            #pragma unroll
            for (int half = 0; half < 2; ++half) {
                int r = mb + mt * 16 + gid + half * 8;
                if (r >= rows) continue;
                #pragma unroll
                for (int nt = 0; nt < 4; ++nt) {
                    int c = nb + nt * 8 + qid * 2;
                    float v0 = silu_f(acc[mt][nt][half * 2 + 0] + bias[c]);
                    float v1 = silu_f(acc[mt][nt][half * 2 + 1] + bias[c + 1]);
                    if (pass) {
                        float h0 = 0.f, h1 = 0.f;
                        #pragma unroll
                        for (int q = 0; q < 6; ++q) {
                            float rv = rbfs[r * 6 + q];
                            h0 += rv * wrbfs[c * 6 + q];
                            h1 += rv * wrbfs[(c + 1) * 6 + q];
                        }
                        v0 *= h0; v1 *= h1;
                    }
                    *(float2*)(dst + (size_t)(e0 + r) * 128 + c) = make_float2(v0, v1);
                }
            }
        }
    }
}

// ---------------------------------------------------------------------------
// K2: bilinear + scatter. 256 triplets x 128 out per CTA, 512 threads =
// 16 warps (8m x 2n), warp tile 32x64. K = 8 (j) x 128.
// xg pre-rounded to tf32 at gather; hot loop scales with plain FMUL and feeds
// raw bits (HMMA.TF32 truncates in HW). Scatter via red.global.add.v4.f32.
// ---------------------------------------------------------------------------
__global__ void __launch_bounds__(512, 1)
k_bil(const float* __restrict__ sbf, const int* __restrict__ idx_kj,
      const int* __restrict__ idx_ji, const float* __restrict__ W_sbf,
      const float* __restrict__ W_bil, int T)
{
    extern __shared__ char smraw[];
    float*    xg  = (float*)smraw;              // [256][LD] gathered x_kj (tf32 bits as float)
    uint32_t* bjm = (uint32_t*)(xg + 256 * LD); // [128][LD] W_bil[:,j,:] tf32, [n][k]
    float*    sbs = (float*)(bjm + 128 * LD);   // [256][8] sbf_b
    int*      ikj = (int*)(sbs + 256 * 8);      // [256]
    int*      iji = ikj + 256;                  // [256]
    float*    wsb = (float*)(iji + 256);        // [8*42]

    const int tid = threadIdx.x, lane = tid & 31, wrp = tid >> 5;
    const int gid = lane >> 2, qid = lane & 3;
    const int mb = (wrp & 7) * 32, nb = (wrp >> 3) * 64;
    const int t0 = blockIdx.x * 256;
    const int rows = min(256, T - t0);

    if (tid < 256) {
        ikj[tid] = (tid < rows) ? idx_kj[t0 + tid] : 0;
        iji[tid] = (tid < rows) ? idx_ji[t0 + tid] : 0;
    }
    for (int i = tid; i < 8 * 42; i += 512) wsb[i] = W_sbf[i];
    // stage sbf rows linearly into xg region
    for (int i = tid; i < 256 * 42; i += 512)
        xg[i] = (i < rows * 42) ? sbf[(size_t)t0 * 42 + i] : 0.f;
    __syncthreads();
    // sbf_b = sbf @ W_sbf^T
    for (int i = tid; i < 256 * 8; i += 512) {
        int r = i >> 3, j = i & 7;
        float s = 0.f;
        #pragma unroll
        for (int q = 0; q < 42; ++q) s += xg[r * 42 + q] * wsb[j * 42 + q];
        sbs[i] = (r < rows) ? s : 0.f;
    }
    __syncthreads();
    // gather x_kj rows, pre-round to tf32 (bits stored as float)
    for (int r = wrp; r < 256; r += 16) {
        float4 v = make_float4(0.f, 0.f, 0.f, 0.f);
        if (r < rows) v = *(const float4*)(g_x_kj + (size_t)ikj[r] * 128 + lane * 4);
        *(uint4*)(xg + r * LD + lane * 4) =
            make_uint4(f2t(v.x), f2t(v.y), f2t(v.z), f2t(v.w));
    }

    float acc[2][8][4];
    #pragma unroll
    for (int mt = 0; mt < 2; ++mt)
        #pragma unroll
        for (int nt = 0; nt < 8; ++nt)
            #pragma unroll
            for (int q = 0; q < 4; ++q) acc[mt][nt][q] = 0.f;

    for (int j = 0; j < 8; ++j) {
        __syncthreads();   // prior-j mma reads of bjm done (also covers gather on j=0)
        for (int i = tid; i < 128 * 32; i += 512) {
            int n = i >> 5, k4 = (i & 31) * 4;
            float4 v = *(const float4*)(W_bil + ((size_t)n * 8 + j) * 128 + k4);
            *(uint4*)(bjm + n * LD + k4) =
                make_uint4(f2t(v.x), f2t(v.y), f2t(v.z), f2t(v.w));
        }
        __syncthreads();

        float sc0, sc1, sc2, sc3;
        {
            int r0 = mb + gid;
            sc0 = sbs[r0 * 8 + j];
            sc1 = sbs[(r0 + 8) * 8 + j];
            sc2 = sbs[(r0 + 16) * 8 + j];
            sc3 = sbs[(r0 + 24) * 8 + j];
        }
        #pragma unroll 2
        for (int ks = 0; ks < 16; ++ks) {
            const int kc = ks * 8 + qid;
            uint32_t a[2][4];
            {
                int r0 = mb + gid;
                a[0][0] = __float_as_uint(xg[r0 * LD + kc]            * sc0);
                a[0][1] = __float_as_uint(xg[(r0 + 8) * LD + kc]      * sc1);
                a[0][2] = __float_as_uint(xg[r0 * LD + kc + 4]        * sc0);
                a[0][3] = __float_as_uint(xg[(r0 + 8) * LD + kc + 4]  * sc1);
                a[1][0] = __float_as_uint(xg[(r0 + 16) * LD + kc]     * sc2);
                a[1][1] = __float_as_uint(xg[(r0 + 24) * LD + kc]     * sc3);
                a[1][2] = __float_as_uint(xg[(r0 + 16) * LD + kc + 4] * sc2);
                a[1][3] = __float_as_uint(xg[(r0 + 24) * LD + kc + 4] * sc3);
            }
            #pragma unroll
            for (int nt = 0; nt < 8; ++nt) {
                int n = nb + nt * 8 + gid;
                uint32_t b0 = bjm[n * LD + kc], b1 = bjm[n * LD + kc + 4];
                mma8(acc[0][nt], a[0], b0, b1);
                mma8(acc[1][nt], a[1], b0, b1);
            }
        }
    }

    __syncthreads();
    // stage C back into xg, then coalesced vector scatter
    #pragma unroll
    for (int mt = 0; mt < 2; ++mt) {
        #pragma unroll
        for (int nt = 0; nt < 8; ++nt) {
            int r0 = mb + mt * 16 + gid;
            int c = nb + nt * 8 + qid * 2;
            *(float2*)(xg + r0 * LD + c)       = make_float2(acc[mt][nt][0], acc[mt][nt][1]);
            *(float2*)(xg + (r0 + 8) * LD + c) = make_float2(acc[mt][nt][2], acc[mt][nt][3]);
        }
    }
    __syncthreads();
    for (int r = wrp; r < rows; r += 16) {
        float4 v = *(const float4*)(xg + r * LD + lane * 4);
        float* p = g_agg + (size_t)iji[r] * 128 + lane * 4;
        asm volatile("red.global.add.v4.f32 [%0], {%1,%2,%3,%4};"
                     :: "l"(p), "f"(v.x), "f"(v.y), "f"(v.z), "f"(v.w) : "memory");
    }
}

// ---------------------------------------------------------------------------
// K3: h = silu(g_agg @ W_lin^T + b_lin). 512 threads, 4m x 4n warps.
// (g_agg already holds x_ji + segment_sum.)
// ---------------------------------------------------------------------------
__global__ void __launch_bounds__(512, 1)
k_out(const float* __restrict__ W_lin, const float* __restrict__ b_lin,
      float* __restrict__ out, int E)
{
    extern __shared__ char smraw[];
    uint32_t* xs = (uint32_t*)smraw;       // [128][LD]
    uint32_t* ws = xs + 128 * LD;          // [128][LD]
    float*    bl = (float*)(ws + 128 * LD);

    const int tid = threadIdx.x, lane = tid & 31, wrp = tid >> 5;
    const int gid = lane >> 2, qid = lane & 3;
    const int mb = (wrp & 3) * 32, nb = (wrp >> 2) * 32;
    const int e0 = blockIdx.x * 128;
    const int rows = min(128, E - e0);

    for (int r = wrp; r < 128; r += 16) {
        float4 v = make_float4(0.f, 0.f, 0.f, 0.f);
        if (r < rows) v = *(const float4*)(g_agg + (size_t)(e0 + r) * 128 + lane * 4);
        *(uint4*)(xs + r * LD + lane * 4) =
            make_uint4(f2t(v.x), f2t(v.y), f2t(v.z), f2t(v.w));
    }
    for (int i = tid; i < 128 * 32; i += 512) {
        int n = i >> 5, k4 = (i & 31) * 4;
        float4 v = *(const float4*)(W_lin + (size_t)n * 128 + k4);
        *(uint4*)(ws + n * LD + k4) =
            make_uint4(f2t(v.x), f2t(v.y), f2t(v.z), f2t(v.w));
    }
    if (tid < 128) bl[tid] = b_lin[tid];
    __syncthreads();

    float acc[2][4][4];
    #pragma unroll
    for (int mt = 0; mt < 2; ++mt)
        #pragma unroll
        for (int nt = 0; nt < 4; ++nt)
            #pragma unroll
            for (int q = 0; q < 4; ++q) acc[mt][nt][q] = 0.f;

    #pragma unroll 4
    for (int ks = 0; ks < 16; ++ks) {
        const int kc = ks * 8 + qid;
        uint32_t a[2][4];
        #pragma unroll
        for (int mt = 0; mt < 2; ++mt) {
            int r0 = mb + mt * 16 + gid;
            a[mt][0] = xs[r0 * LD + kc];
            a[mt][1] = xs[(r0 + 8) * LD + kc];
            a[mt][2] = xs[r0 * LD + kc + 4];
            a[mt][3] = xs[(r0 + 8) * LD + kc + 4];
        }
        #pragma unroll
        for (int nt = 0; nt < 4; ++nt) {
            int n = nb + nt * 8 + gid;
            uint32_t b0 = ws[n * LD + kc], b1 = ws[n * LD + kc + 4];
            mma8(acc[0][nt], a[0], b0, b1);
            mma8(acc[1][nt], a[1], b0, b1);
        }
    }

    #pragma unroll
    for (int mt = 0; mt < 2; ++mt) {
        #pragma unroll
        for (int half = 0; half < 2; ++half) {
            int r = mb + mt * 16 + gid + half * 8;
            if (r >= rows) continue;
            #pragma unroll
            for (int nt = 0; nt < 4; ++nt) {
                int c = nb + nt * 8 + qid * 2;
                float v0 = silu_f(acc[mt][nt][half * 2 + 0] + bl[c]);
                float v1 = silu_f(acc[mt][nt][half * 2 + 1] + bl[c + 1]);
                *(float2*)(out + (size_t)(e0 + r) * 128 + c) = make_float2(v0, v1);
            }
        }
    }
}

// ---------------------------------------------------------------------------
extern "C" void kernel_launch(void* const* d_in, const int* in_sizes, int n_in,
                              void* d_out, int out_size)
{
    const float* x     = (const float*)d_in[0];
    const float* rbf   = (const float*)d_in[1];
    const float* sbf   = (const float*)d_in[2];
    const int*   ikj   = (const int*)d_in[3];
    const int*   iji   = (const int*)d_in[4];
    const float* W_rbf = (const float*)d_in[5];
    const float* W_sbf = (const float*)d_in[6];
    const float* W_kj  = (const float*)d_in[7];
    const float* b_kj  = (const float*)d_in[8];
    const float* W_ji  = (const float*)d_in[9];
    const float* b_ji  = (const float*)d_in[10];
    const float* W_bil = (const float*)d_in[11];
    const float* W_lin = (const float*)d_in[12];
    const float* b_lin = (const float*)d_in[13];

    const int E = in_sizes[0] / 128;
    const int T = in_sizes[3];

    const int SM1 = 128 * LD * 4 * 2 + 128 * 6 * 4 * 2 + 256 * 4;                     // 142336
    const int SM2 = 256 * LD * 4 + 128 * LD * 4 + 256 * 8 * 4 + 512 * 4 + 8 * 42 * 4; // 214336
    const int SM3 = 128 * LD * 4 * 2 + 128 * 4;                                       // 135680

    cudaFuncSetAttribute(k_edge, cudaFuncAttributeMaxDynamicSharedMemorySize, SM1);
    cudaFuncSetAttribute(k_bil,  cudaFuncAttributeMaxDynamicSharedMemorySize, SM2);
    cudaFuncSetAttribute(k_out,  cudaFuncAttributeMaxDynamicSharedMemorySize, SM3);

    dim3 blk(512);
    k_edge<<<(E + 127) / 128, blk, SM1>>>(x, rbf, W_rbf, W_kj, b_kj, W_ji, b_ji, E);
    k_bil <<<(T + 255) / 256, blk, SM2>>>(sbf, ikj, iji, W_sbf, W_bil, T);
    k_out <<<(E + 127) / 128, blk, SM3>>>(W_lin, b_lin, (float*)d_out, E);
}